// round 4
// baseline (speedup 1.0000x reference)
#include <cuda_runtime.h>

// out[b,i] = g[b, i>>7] * (W[i,:] . x[b,:]) + bias[i]
// where g = sigmoid(x @ gate_w + gate_b) with the 8 smallest gates per row zeroed.
//
// Kernel 1 (gemm_gate): 256 GEMM blocks (16 row-tiles x 16 k-tiles) writing
//   deterministic split-K partials, plus 32 gate blocks (one per batch sample)
//   computing the gate network concurrently.
// Kernel 2 (finish): sum 16 partials, apply gate + bias.

#define BATCH 32
#define DIM   2048
#define NGATE 16
#define KT    16            // split-K factor
#define KC    (DIM / KT)    // 128 k-elements per block
#define RT    16            // row tiles
#define RROWS 128           // rows per tile (= threads per block)
#define GEMM_BLOCKS (RT * KT)
#define THREADS 128

__device__ float g_gates[BATCH * NGATE];
__device__ float g_part[KT * BATCH * DIM];   // 4 MB split-K partials

// Packed dual-FMA: d.{lo,hi} += a.{lo,hi} * b.{lo,hi}  (sm_100+ f32x2 pipe)
__device__ __forceinline__ void ffma2(unsigned long long& d,
                                      unsigned long long a,
                                      unsigned long long b) {
    asm("fma.rn.f32x2 %0, %1, %2, %0;" : "+l"(d) : "l"(a), "l"(b));
}

__device__ __forceinline__ float2 unpack2(unsigned long long v) {
    float2 r;
    asm("mov.b64 {%0, %1}, %2;" : "=f"(r.x), "=f"(r.y) : "l"(v));
    return r;
}

__global__ __launch_bounds__(THREADS)
void gemm_gate_kernel(const float* __restrict__ x,
                      const float* __restrict__ gate_w,
                      const float* __restrict__ gate_b,
                      const float* __restrict__ weight) {
    __shared__ __align__(16) float smem[BATCH * KC];  // 16 KB: x chunk xs[b][j]
    const int tid = threadIdx.x;
    const int gb  = blockIdx.x;

    if (gb < GEMM_BLOCKS) {
        // ---------------- GEMM block ----------------
        const int rt = gb & (RT - 1);
        const int kt = gb >> 4;
        const int j0 = kt * KC;

        // Stage x chunk into smem: xs[b][j], pitch KC floats.
        // Coalesced float4 loads, conflict-free float4 stores.
        {
            const float4* X4  = (const float4*)x;
            float4*       xs4 = (float4*)smem;
#pragma unroll
            for (int idx = tid; idx < BATCH * KC / 4; idx += THREADS) {
                const int bb = idx >> 5;       // batch
                const int j4 = idx & 31;       // float4 within chunk
                xs4[idx] = X4[bb * (DIM / 4) + (j0 >> 2) + j4];
            }
        }
        __syncthreads();

        const int i = rt * RROWS + tid;        // output row owned by this thread
        const ulonglong2* __restrict__ W2 =
            (const ulonglong2*)(weight + (size_t)i * DIM + j0);
        const ulonglong2* xs2 = (const ulonglong2*)smem;  // row pitch = KC/4 vec

        unsigned long long acc[BATCH];         // f32x2 pair per batch (even/odd j)
#pragma unroll
        for (int b = 0; b < BATCH; ++b) acc[b] = 0ull;

        // Software-pipelined W row: 1 LDG.128 feeds 64 FFMA2.
        ulonglong2 wa = W2[0];
        ulonglong2 wb = W2[1];
#pragma unroll 4
        for (int jj = 0; jj < KC / 4; ++jj) {
            const ulonglong2 wc = wa;
            wa = wb;
            wb = (jj + 2 < KC / 4) ? W2[jj + 2] : wa;   // guard OOB on tail
            const ulonglong2* xrow = xs2 + jj;          // broadcast across warp
#pragma unroll
            for (int b = 0; b < BATCH; ++b) {
                const ulonglong2 xv = xrow[b * (KC / 4)];
                ffma2(acc[b], wc.x, xv.x);   // j, j+1
                ffma2(acc[b], wc.y, xv.y);   // j+2, j+3
            }
        }

        float* part = g_part + (size_t)kt * (BATCH * DIM) + i;
#pragma unroll
        for (int b = 0; b < BATCH; ++b) {
            const float2 v = unpack2(acc[b]);
            part[b * DIM] = v.x + v.y;       // coalesced across lanes
        }
    } else {
        // ---------------- gate block (one per batch sample) ----------------
        const int b = gb - GEMM_BLOCKS;
        float* red = smem;            // [128] partial dots
        float* sg  = smem + 128;      // [16] sigmoid gates
        const int nb = tid >> 3;      // gate index 0..15
        const int pp = tid & 7;       // 8-way k partition
        const float* xb = x + b * DIM;

        float a0 = 0.f, a1 = 0.f, a2 = 0.f, a3 = 0.f;
#pragma unroll 4
        for (int j = pp * 4; j < DIM; j += 32) {
            const float4 xv = *(const float4*)(xb + j);
            a0 += xv.x * gate_w[(j + 0) * NGATE + nb];
            a1 += xv.y * gate_w[(j + 1) * NGATE + nb];
            a2 += xv.z * gate_w[(j + 2) * NGATE + nb];
            a3 += xv.w * gate_w[(j + 3) * NGATE + nb];
        }
        red[tid] = (a0 + a1) + (a2 + a3);
        __syncthreads();

        if (tid < NGATE) {
            float s = gate_b[tid];
#pragma unroll
            for (int p = 0; p < 8; ++p) s += red[tid * 8 + p];
            sg[tid] = 1.0f / (1.0f + expf(-s));
        }
        __syncthreads();

        if (tid < NGATE) {
            const float v = sg[tid];
            // ascending rank with jax top_k tie-break (lower index dropped first)
            int rank = 0;
#pragma unroll
            for (int j = 0; j < NGATE; ++j) {
                const float u = sg[j];
                rank += (u < v) || (u == v && j < tid);
            }
            g_gates[b * NGATE + tid] = (rank >= NGATE / 2) ? v : 0.0f;
        }
    }
}

__global__ __launch_bounds__(THREADS)
void finish_kernel(const float* __restrict__ bias, float* __restrict__ out) {
    const int t = blockIdx.x * blockDim.x + threadIdx.x;  // 0..16383 (float4 units)
    const float4* P4 = (const float4*)g_part;
    float4 s = make_float4(0.f, 0.f, 0.f, 0.f);
#pragma unroll
    for (int kt = 0; kt < KT; ++kt) {
        const float4 p = P4[kt * (BATCH * DIM / 4) + t];
        s.x += p.x; s.y += p.y; s.z += p.z; s.w += p.w;
    }
    const int b = t >> 9;               // 512 float4 per row
    const int i = (t & 511) * 4;
    const float g  = g_gates[b * NGATE + (i >> 7)];
    const float4 bv = ((const float4*)bias)[t & 511];
    float4 o;
    o.x = g * s.x + bv.x;
    o.y = g * s.y + bv.y;
    o.z = g * s.z + bv.z;
    o.w = g * s.w + bv.w;
    ((float4*)out)[t] = o;
}

extern "C" void kernel_launch(void* const* d_in, const int* in_sizes, int n_in,
                              void* d_out, int out_size) {
    const float* x      = (const float*)d_in[0];
    const float* gate_w = (const float*)d_in[1];
    const float* gate_b = (const float*)d_in[2];
    const float* weight = (const float*)d_in[3];
    const float* bias   = (const float*)d_in[4];
    float* out = (float*)d_out;

    gemm_gate_kernel<<<GEMM_BLOCKS + BATCH, THREADS>>>(x, gate_w, gate_b, weight);
    finish_kernel<<<(BATCH * DIM / 4) / THREADS, THREADS>>>(bias, out);
}

// round 5
// speedup vs baseline: 1.0933x; 1.0933x over previous
#include <cuda_runtime.h>

// out[b,i] = g[b, i>>7] * (W[i,:] . x[b,:]) + bias[i]
// g = sigmoid(x @ gate_w + gate_b), 8 smallest gates per row zeroed.
//
// R5: GEMM blocks = 128 (8 row-tiles x 16 k-tiles), each thread owns 2 rows
// x 32 batches with depth-4 W prefetch per row (8 LDG.128 in flight/thread).
// 16 gate blocks (2 batches each) -> 144 total blocks = one clean wave.
// finish: 1 thread/output element, 16 scalar in-flight loads.

#define BATCH 32
#define DIM   2048
#define NGATE 16
#define KT    16            // split-K factor
#define KC    (DIM / KT)    // 128 k-elements per block
#define KCV   (KC / 4)      // 32 ulonglong2 steps
#define RT    8             // row tiles (256 rows each)
#define GEMM_BLOCKS (RT * KT)     // 128
#define GATE_BLOCKS (BATCH / 2)   // 16
#define THREADS 128

__device__ float g_gates[BATCH * NGATE];
__device__ float g_part[KT * BATCH * DIM];   // 4 MB split-K partials

// Packed dual-FMA: d.{lo,hi} += a.{lo,hi} * b.{lo,hi}  (sm_100+ f32x2 pipe)
__device__ __forceinline__ void ffma2(unsigned long long& d,
                                      unsigned long long a,
                                      unsigned long long b) {
    asm("fma.rn.f32x2 %0, %1, %2, %0;" : "+l"(d) : "l"(a), "l"(b));
}

__device__ __forceinline__ float2 unpack2(unsigned long long v) {
    float2 r;
    asm("mov.b64 {%0, %1}, %2;" : "=f"(r.x), "=f"(r.y) : "l"(v));
    return r;
}

__global__ __launch_bounds__(THREADS)
void gemm_gate_kernel(const float* __restrict__ x,
                      const float* __restrict__ gate_w,
                      const float* __restrict__ gate_b,
                      const float* __restrict__ weight) {
    __shared__ __align__(16) float smem[BATCH * KC];  // 16 KB x chunk xs[b][j]
    const int tid = threadIdx.x;
    const int gb  = blockIdx.x;

    if (gb < GEMM_BLOCKS) {
        // ---------------- GEMM block: 256 rows x 32 batches x KC k ----------
        const int rt = gb & (RT - 1);
        const int kt = gb >> 3;
        const int j0 = kt * KC;

        // Stage x chunk: xs[b][j] (pitch KC). Coalesced float4.
        {
            const float4* X4  = (const float4*)x;
            float4*       xs4 = (float4*)smem;
#pragma unroll
            for (int idx = tid; idx < BATCH * KCV; idx += THREADS) {
                const int bb = idx >> 5;
                const int j4 = idx & 31;
                xs4[idx] = X4[bb * (DIM / 4) + (j0 >> 2) + j4];
            }
        }
        __syncthreads();

        const int i0 = rt * 256 + tid;     // first owned row
        const int i1 = i0 + 128;           // second owned row
        const ulonglong2* __restrict__ Wa =
            (const ulonglong2*)(weight + (size_t)i0 * DIM + j0);
        const ulonglong2* __restrict__ Wb =
            (const ulonglong2*)(weight + (size_t)i1 * DIM + j0);
        const ulonglong2* xs2 = (const ulonglong2*)smem;   // pitch KCV

        unsigned long long accA[BATCH], accB[BATCH];
#pragma unroll
        for (int b = 0; b < BATCH; ++b) { accA[b] = 0ull; accB[b] = 0ull; }

        // Depth-4 prefetch ring per row: 8 LDG.128 in flight per thread.
        ulonglong2 bufA[4], bufB[4];
#pragma unroll
        for (int p = 0; p < 4; ++p) { bufA[p] = Wa[p]; bufB[p] = Wb[p]; }

        for (int base = 0; base < KCV; base += 4) {        // rolled outer
#pragma unroll
            for (int c = 0; c < 4; ++c) {
                const ulonglong2 wA = bufA[c];
                const ulonglong2 wB = bufB[c];
                const int nj = base + 4 + c;
                if (nj < KCV) { bufA[c] = Wa[nj]; bufB[c] = Wb[nj]; }
                const ulonglong2* xrow = xs2 + (base + c);
#pragma unroll
                for (int b = 0; b < BATCH; ++b) {
                    const ulonglong2 xv = xrow[b * KCV];   // warp broadcast
                    ffma2(accA[b], wA.x, xv.x);
                    ffma2(accA[b], wA.y, xv.y);
                    ffma2(accB[b], wB.x, xv.x);
                    ffma2(accB[b], wB.y, xv.y);
                }
            }
        }

        float* pA = g_part + (size_t)kt * (BATCH * DIM) + i0;
        float* pB = g_part + (size_t)kt * (BATCH * DIM) + i1;
#pragma unroll
        for (int b = 0; b < BATCH; ++b) {
            const float2 va = unpack2(accA[b]);
            const float2 vb = unpack2(accB[b]);
            pA[b * DIM] = va.x + va.y;     // coalesced across lanes
            pB[b * DIM] = vb.x + vb.y;
        }
    } else {
        // ---------------- gate block: 2 batch samples ----------------------
        const int b0 = (gb - GEMM_BLOCKS) * 2;
        float* red = smem;           // [128]
        float* sg  = smem + 128;     // [16]
        const int nb = tid >> 3;     // gate index 0..15
        const int pp = tid & 7;      // 8-way k partition

        for (int u = 0; u < 2; ++u) {
            const int b = b0 + u;
            const float* xb = x + b * DIM;
            float a0 = 0.f, a1 = 0.f, a2 = 0.f, a3 = 0.f;
#pragma unroll 4
            for (int j = pp * 4; j < DIM; j += 32) {
                const float4 xv = *(const float4*)(xb + j);
                a0 += xv.x * gate_w[(j + 0) * NGATE + nb];
                a1 += xv.y * gate_w[(j + 1) * NGATE + nb];
                a2 += xv.z * gate_w[(j + 2) * NGATE + nb];
                a3 += xv.w * gate_w[(j + 3) * NGATE + nb];
            }
            red[tid] = (a0 + a1) + (a2 + a3);
            __syncthreads();

            if (tid < NGATE) {
                float s = gate_b[tid];
#pragma unroll
                for (int p = 0; p < 8; ++p) s += red[tid * 8 + p];
                sg[tid] = 1.0f / (1.0f + expf(-s));
            }
            __syncthreads();

            if (tid < NGATE) {
                const float v = sg[tid];
                int rank = 0;   // ascending rank, jax top_k tie-break
#pragma unroll
                for (int j = 0; j < NGATE; ++j) {
                    const float u2 = sg[j];
                    rank += (u2 < v) || (u2 == v && j < tid);
                }
                g_gates[b * NGATE + tid] = (rank >= NGATE / 2) ? v : 0.0f;
            }
            __syncthreads();
        }
    }
}

__global__ __launch_bounds__(256)
void finish_kernel(const float* __restrict__ bias, float* __restrict__ out) {
    const int t = blockIdx.x * 256 + threadIdx.x;   // 0..65535, one per element
    float p[KT];
#pragma unroll
    for (int kt = 0; kt < KT; ++kt) p[kt] = g_part[kt * (BATCH * DIM) + t];
    float s = 0.f;
#pragma unroll
    for (int kt = 0; kt < KT; ++kt) s += p[kt];     // fixed order: deterministic
    const int b = t >> 11;
    const int i = t & (DIM - 1);
    const float g = g_gates[b * NGATE + (i >> 7)];
    out[t] = g * s + bias[i];
}

extern "C" void kernel_launch(void* const* d_in, const int* in_sizes, int n_in,
                              void* d_out, int out_size) {
    const float* x      = (const float*)d_in[0];
    const float* gate_w = (const float*)d_in[1];
    const float* gate_b = (const float*)d_in[2];
    const float* weight = (const float*)d_in[3];
    const float* bias   = (const float*)d_in[4];
    float* out = (float*)d_out;

    gemm_gate_kernel<<<GEMM_BLOCKS + GATE_BLOCKS, THREADS>>>(x, gate_w, gate_b, weight);
    finish_kernel<<<(BATCH * DIM) / 256, 256>>>(bias, out);
}